// round 12
// baseline (speedup 1.0000x reference)
#include <cuda_runtime.h>
#include <cstdint>

#define BATCH    4096
#define NINTRS   256
#define NATOMS   256
#define DATA_DIM 28
#define KSTRIDE  29
#define M_BATCH  524288
#define RPC      8      // rays per CTA in bred kernel

__device__ int    g_cnt[BATCH];
__device__ int    g_rowoff[BATCH];
__device__ float4 g_bred[BATCH * NATOMS];   // 16MB per-ray reduced matrices

// ---------------------------------------------------------------------------
// cp.async helpers (per-thread groups; each lane consumes only its own slots,
// so no cross-thread sync is needed for the stream pipeline).
// ---------------------------------------------------------------------------
__device__ __forceinline__ uint32_t smem_u32(const void* p) {
    return (uint32_t)__cvta_generic_to_shared(p);
}
#define CP_ASYNC16(dst, src) \
    asm volatile("cp.async.cg.shared.global [%0], [%1], 16;" :: "r"(dst), "l"(src))
#define CP_COMMIT()  asm volatile("cp.async.commit_group;")
#define CP_WAIT2()   asm volatile("cp.async.wait_group 2;")
#define CP_WAIT0()   asm volatile("cp.async.wait_group 0;")

// ---------------------------------------------------------------------------
// Mask dtype auto-detection (uint8 / int32 / float32), deterministic.
// ---------------------------------------------------------------------------
__device__ __forceinline__ unsigned mask_mode(const void* m) {
    unsigned w0 = *reinterpret_cast<const unsigned*>(m);
    if (w0 == 0x3F800000u) return 2u;   // float32
    if (w0 == 1u)          return 1u;   // int32
    return 0u;                          // byte / bool
}
__device__ __forceinline__ int mask_at(const void* m, unsigned mode, long i) {
    if (mode == 1u) return reinterpret_cast<const int*>(m)[i] != 0;
    if (mode == 2u) return reinterpret_cast<const float*>(m)[i] != 0.0f;
    return reinterpret_cast<const unsigned char*>(m)[i] != 0;
}

// ---------------------------------------------------------------------------
// Kernel A: per-ray valid count, warp per ray, vectorized per dtype mode.
// ---------------------------------------------------------------------------
__global__ void count_kernel(const void* __restrict__ mask) {
    unsigned mode = mask_mode(mask);
    int ray  = blockIdx.x * 8 + (threadIdx.x >> 5);
    int lane = threadIdx.x & 31;
    int s = 0;
    if (mode == 0u) {
        const uint2* mp = reinterpret_cast<const uint2*>(
            reinterpret_cast<const unsigned char*>(mask) + (size_t)ray * NINTRS);
        uint2 v = mp[lane];
        s = (__popc(__vcmpne4(v.x, 0u)) + __popc(__vcmpne4(v.y, 0u))) >> 3;
    } else if (mode == 1u) {
        const int4* mp = reinterpret_cast<const int4*>(
            reinterpret_cast<const int*>(mask) + (size_t)ray * NINTRS);
        int4 a = mp[lane], b = mp[lane + 32];
        s = (a.x != 0) + (a.y != 0) + (a.z != 0) + (a.w != 0)
          + (b.x != 0) + (b.y != 0) + (b.z != 0) + (b.w != 0);
    } else {
        const float4* mp = reinterpret_cast<const float4*>(
            reinterpret_cast<const float*>(mask) + (size_t)ray * NINTRS);
        float4 a = mp[lane], b = mp[lane + 32];
        s = (a.x != 0.f) + (a.y != 0.f) + (a.z != 0.f) + (a.w != 0.f)
          + (b.x != 0.f) + (b.y != 0.f) + (b.z != 0.f) + (b.w != 0.f);
    }
    #pragma unroll
    for (int o = 16; o; o >>= 1) s += __shfl_down_sync(0xffffffffu, s, o);
    if (lane == 0) g_cnt[ray] = s;
}

// ---------------------------------------------------------------------------
// Kernel B: exclusive scan of per-ray counts (shfl-based, 2 barriers).
// ---------------------------------------------------------------------------
__global__ void scan_kernel() {
    __shared__ int warp_tot[32];
    int t = threadIdx.x, lane = t & 31, w = t >> 5;
    int a[4];
    int s = 0;
    #pragma unroll
    for (int j = 0; j < 4; j++) { a[j] = g_cnt[t * 4 + j]; s += a[j]; }
    int x = s;
    #pragma unroll
    for (int o = 1; o < 32; o <<= 1) {
        int v = __shfl_up_sync(0xffffffffu, x, o);
        if (lane >= o) x += v;
    }
    if (lane == 31) warp_tot[w] = x;
    __syncthreads();
    if (w == 0) {
        int y = warp_tot[lane];
        #pragma unroll
        for (int o = 1; o < 32; o <<= 1) {
            int v = __shfl_up_sync(0xffffffffu, y, o);
            if (lane >= o) y += v;
        }
        warp_tot[lane] = y;
    }
    __syncthreads();
    int base = ((w > 0) ? warp_tot[w - 1] : 0) + (x - s);  // exclusive prefix
    #pragma unroll
    for (int j = 0; j < 4; j++) { g_rowoff[t * 4 + j] = base; base += a[j]; }
}

// ---------------------------------------------------------------------------
// Kernel C: per-ray reduced matrices. CTA handles RPC rays; atoms staged once.
// Bred[ray][k] = (sh . atoms[k,0:9], sh . atoms[k,9:18], sh . atoms[k,18:27],
//                 atoms[k,27])
// ---------------------------------------------------------------------------
__global__ void __launch_bounds__(256)
bred_kernel(const float* __restrict__ rays_d, const float* __restrict__ atoms) {
    __shared__ float sa[NATOMS * KSTRIDE];
    __shared__ float ssh[RPC][12];
    int tid = threadIdx.x;

    #pragma unroll
    for (int it = 0; it < DATA_DIM; it++) {
        int idx = tid + it * 256;
        int r = idx / DATA_DIM;
        int c = idx - r * DATA_DIM;
        sa[r * KSTRIDE + c] = atoms[idx];
    }
    if (tid < RPC) {
        int ray = blockIdx.x * RPC + tid;
        float dx = rays_d[ray * 3 + 0], dy = rays_d[ray * 3 + 1], dz = rays_d[ray * 3 + 2];
        float n = sqrtf(dx * dx + dy * dy + dz * dz);
        float inv = 1.0f / n;
        float x = dx * inv, y = dy * inv, z = dz * inv;
        const float C1 = 0.4886025119029199f;
        ssh[tid][0] = 0.28209479177387814f;
        ssh[tid][1] = -C1 * y;
        ssh[tid][2] =  C1 * z;
        ssh[tid][3] = -C1 * x;
        ssh[tid][4] =  1.0925484305920792f * x * y;
        ssh[tid][5] = -1.0925484305920792f * y * z;
        ssh[tid][6] =  0.31539156525252005f * (2.0f * z * z - x * x - y * y);
        ssh[tid][7] = -1.0925484305920792f * x * z;
        ssh[tid][8] =  0.5462742152960396f * (x * x - y * y);
    }
    __syncthreads();

    float ar[DATA_DIM];
    #pragma unroll
    for (int c = 0; c < DATA_DIM; c++) ar[c] = sa[tid * KSTRIDE + c];

    #pragma unroll
    for (int rr = 0; rr < RPC; rr++) {
        int ray = blockIdx.x * RPC + rr;
        float c0 = 0.f, c1 = 0.f, c2 = 0.f;
        #pragma unroll
        for (int s = 0; s < 9; s++) {
            float bs = ssh[rr][s];
            c0 = fmaf(bs, ar[s],      c0);
            c1 = fmaf(bs, ar[9 + s],  c1);
            c2 = fmaf(bs, ar[18 + s], c2);
        }
        g_bred[(size_t)ray * NATOMS + tid] = make_float4(c0, c1, c2, ar[27]);
    }
}

// ---------------------------------------------------------------------------
// Kernel D: fused render. One CTA per ray, 256 threads.
// GEMM streams `queries` through a per-lane 4-stage cp.async pipeline.
// ---------------------------------------------------------------------------
__global__ void __launch_bounds__(256)
render_kernel(const float* __restrict__ rays_d,
              const float* __restrict__ queries,
              const void*  __restrict__ mask,
              const float* __restrict__ inter,
              float* __restrict__ out_rgb,
              float* __restrict__ out_alpha,
              float* __restrict__ out_depth)
{
    // stage layout: [warp][stage]{ qa: lane*16B (512B) | qb: 512 + lane*16B }
    __shared__ float  s_stage[8 * 4 * 256];   // 32KB
    __shared__ float4 s_res[NINTRS];          // 4KB
    __shared__ int    s_wcnt[8];
    __shared__ float  s_wprod[8];
    __shared__ float  s_red[5][8];

    const int b    = blockIdx.x;
    const int tid  = threadIdx.x;
    const int lane = tid & 31;
    const int wid  = tid >> 5;

    // ---- mask + compaction rank ----
    const unsigned mmode = mask_mode(mask);
    const int mbit = mask_at(mask, mmode, (long)b * NINTRS + tid);
    unsigned bal = __ballot_sync(0xffffffffu, (unsigned)mbit);
    int lprefix = __popc(bal & ((1u << lane) - 1u));
    if (lane == 0) s_wcnt[wid] = __popc(bal);
    __syncthreads();

    int woff = 0, cnt_b = 0;
    #pragma unroll
    for (int w = 0; w < 8; w++) {
        int c = s_wcnt[w];
        if (w < wid) woff += c;
        cnt_b += c;
    }
    const int local_pos = woff + lprefix;
    const int rowbase   = g_rowoff[b];

    // ---- Bred slice straight from gmem (coalesced 64B/lane chunks) ----
    const float4* bred = g_bred + (size_t)b * NATOMS;
    float4 Bt[8];
    #pragma unroll
    for (int j = 0; j < 4; j++) Bt[j]     = bred[lane * 4 + j];
    #pragma unroll
    for (int j = 0; j < 4; j++) Bt[4 + j] = bred[128 + lane * 4 + j];

    // ---- GEMM with cp.async pipeline: warp handles rows wid, wid+8, ... ----
    const int nrows = (cnt_b > wid) ? ((cnt_b - wid - 1) >> 3) + 1 : 0;
    const char* qbytes = reinterpret_cast<const char*>(queries);
    const uint32_t stage_b = smem_u32(s_stage) + wid * 4096 + lane * 16;
    const int row_max = cnt_b - 1;

    if (nrows > 0) {
        // prologue: 3 groups in flight
        #pragma unroll
        for (int r = 0; r < 3; r++) {
            int row = min(wid + 8 * r, row_max);
            const char* src = qbytes + (size_t)(rowbase + row) * 1024 + lane * 16;
            uint32_t d = stage_b + (r & 3) * 1024;
            CP_ASYNC16(d, src);
            CP_ASYNC16(d + 512, src + 512);
            CP_COMMIT();
        }
        for (int r = 0; r < nrows; r++) {
            CP_WAIT2();  // oldest group (stage r) complete
            int fidx = wid * 1024 + (r & 3) * 256 + lane * 4;
            float4 qa = *reinterpret_cast<float4*>(&s_stage[fidx]);
            float4 qb = *reinterpret_cast<float4*>(&s_stage[fidx + 128]);
            // prefetch row r+3
            {
                int row = min(wid + 8 * (r + 3), row_max);
                const char* src = qbytes + (size_t)(rowbase + row) * 1024 + lane * 16;
                uint32_t d = stage_b + ((r + 3) & 3) * 1024;
                CP_ASYNC16(d, src);
                CP_ASYNC16(d + 512, src + 512);
                CP_COMMIT();
            }
            float4 acc = make_float4(0.f, 0.f, 0.f, 0.f);
            #define ACC4(qv, bt) { \
                acc.x = fmaf(qv, bt.x, acc.x); acc.y = fmaf(qv, bt.y, acc.y); \
                acc.z = fmaf(qv, bt.z, acc.z); acc.w = fmaf(qv, bt.w, acc.w); }
            ACC4(qa.x, Bt[0]); ACC4(qa.y, Bt[1]); ACC4(qa.z, Bt[2]); ACC4(qa.w, Bt[3]);
            ACC4(qb.x, Bt[4]); ACC4(qb.y, Bt[5]); ACC4(qb.z, Bt[6]); ACC4(qb.w, Bt[7]);
            #undef ACC4
            #pragma unroll
            for (int o = 16; o; o >>= 1) {
                acc.x += __shfl_down_sync(0xffffffffu, acc.x, o);
                acc.y += __shfl_down_sync(0xffffffffu, acc.y, o);
                acc.z += __shfl_down_sync(0xffffffffu, acc.z, o);
                acc.w += __shfl_down_sync(0xffffffffu, acc.w, o);
            }
            if (lane == 0) s_res[wid + 8 * r] = acc;
        }
        CP_WAIT0();
    }
    __syncthreads();

    // ---- rendering: thread i = intersection i ----
    float4 r4 = make_float4(0.f, 0.f, 0.f, 0.f);
    if (mbit) r4 = s_res[local_pos];
    float sigma = fmaxf(r4.w, 0.0f);
    float dx = rays_d[b * 3 + 0], dy = rays_d[b * 3 + 1], dz = rays_d[b * 3 + 2];
    float dn = sqrtf(dx * dx + dy * dy + dz * dz);
    const float* ib = inter + (size_t)b * (NINTRS + 1);
    float t0 = ib[tid], t1 = ib[tid + 1];
    float delta = t1 - t0;
    float alpha = 1.0f - expf(-sigma * delta * dn);
    float p = 1.0f - alpha + 1e-10f;

    // exclusive product scan -> transmittance
    float incl = p;
    #pragma unroll
    for (int o = 1; o < 32; o <<= 1) {
        float v = __shfl_up_sync(0xffffffffu, incl, o);
        if (lane >= o) incl *= v;
    }
    if (lane == 31) s_wprod[wid] = incl;
    float prev = __shfl_up_sync(0xffffffffu, incl, 1);
    float excl_w = (lane == 0) ? 1.0f : prev;
    __syncthreads();
    float wpre = 1.0f;
    #pragma unroll
    for (int w = 0; w < 8; w++) if (w < wid) wpre *= s_wprod[w];
    float trans = wpre * excl_w;
    float wgt = alpha * trans;

    float sgx = 1.0f / (1.0f + expf(-r4.x));
    float sgy = 1.0f / (1.0f + expf(-r4.y));
    float sgz = 1.0f / (1.0f + expf(-r4.z));
    float tmid = 0.5f * (t0 + t1);

    float v0 = wgt, v1 = wgt * sgx, v2 = wgt * sgy, v3 = wgt * sgz, v4 = wgt * tmid;
    #pragma unroll
    for (int o = 16; o; o >>= 1) {
        v0 += __shfl_down_sync(0xffffffffu, v0, o);
        v1 += __shfl_down_sync(0xffffffffu, v1, o);
        v2 += __shfl_down_sync(0xffffffffu, v2, o);
        v3 += __shfl_down_sync(0xffffffffu, v3, o);
        v4 += __shfl_down_sync(0xffffffffu, v4, o);
    }
    if (lane == 0) {
        s_red[0][wid] = v0; s_red[1][wid] = v1; s_red[2][wid] = v2;
        s_red[3][wid] = v3; s_red[4][wid] = v4;
    }
    __syncthreads();
    if (tid == 0) {
        float S = 0.f, R0 = 0.f, R1 = 0.f, R2 = 0.f, D = 0.f;
        #pragma unroll
        for (int w = 0; w < 8; w++) {
            S  += s_red[0][w]; R0 += s_red[1][w]; R1 += s_red[2][w];
            R2 += s_red[3][w]; D  += s_red[4][w];
        }
        float bg = 1.0f - S;
        out_rgb[b * 3 + 0] = R0 + bg;
        out_rgb[b * 3 + 1] = R1 + bg;
        out_rgb[b * 3 + 2] = R2 + bg;
        out_depth[b] = D;
    }
    out_alpha[(size_t)b * NINTRS + tid] = alpha;
}

// ---------------------------------------------------------------------------
// Launch. Inputs bound BY ELEMENT COUNT (ordering-proof):
//   rays_d 12288 | queries 134217728 | mask 1048576 | inter 1052672 | atoms 7168
// ---------------------------------------------------------------------------
extern "C" void kernel_launch(void* const* d_in, const int* in_sizes, int n_in,
                              void* d_out, int out_size) {
    const float* rays_d  = nullptr;
    const float* queries = nullptr;
    const void*  qmask   = nullptr;
    const float* inter   = nullptr;
    const float* atoms   = nullptr;

    for (int i = 0; i < n_in; i++) {
        switch (in_sizes[i]) {
            case 12288:      rays_d  = (const float*)d_in[i]; break;
            case 134217728:  queries = (const float*)d_in[i]; break;
            case 1048576:    qmask   = d_in[i];               break;
            case 1052672:    inter   = (const float*)d_in[i]; break;
            case 7168:       atoms   = (const float*)d_in[i]; break;
            default: break;
        }
    }

    float* out       = (float*)d_out;
    float* out_rgb   = out;
    float* out_alpha = out + BATCH * 3;
    float* out_depth = out + BATCH * 3 + (size_t)BATCH * NINTRS;

    count_kernel<<<BATCH / 8, 256>>>(qmask);
    scan_kernel<<<1, 1024>>>();
    bred_kernel<<<BATCH / RPC, 256>>>(rays_d, atoms);
    render_kernel<<<BATCH, 256>>>(rays_d, queries, qmask, inter,
                                  out_rgb, out_alpha, out_depth);
}

// round 16
// speedup vs baseline: 1.4890x; 1.4890x over previous
#include <cuda_runtime.h>
#include <cstdint>

#define BATCH    4096
#define NINTRS   256
#define NATOMS   256
#define DATA_DIM 28
#define KSTRIDE  29
#define RPC      8      // rays per CTA in bred kernel

__device__ int    g_cnt[BATCH];
__device__ int    g_rowoff[BATCH];
__device__ float4 g_bred[BATCH * NATOMS];   // 16MB per-ray reduced matrices

// ---------------------------------------------------------------------------
// Mask dtype auto-detection (uint8 / int32 / float32), deterministic.
// ---------------------------------------------------------------------------
__device__ __forceinline__ unsigned mask_mode(const void* m) {
    unsigned w0 = *reinterpret_cast<const unsigned*>(m);
    if (w0 == 0x3F800000u) return 2u;   // float32
    if (w0 == 1u)          return 1u;   // int32
    return 0u;                          // byte / bool
}
__device__ __forceinline__ int mask_at(const void* m, unsigned mode, long i) {
    if (mode == 1u) return reinterpret_cast<const int*>(m)[i] != 0;
    if (mode == 2u) return reinterpret_cast<const float*>(m)[i] != 0.0f;
    return reinterpret_cast<const unsigned char*>(m)[i] != 0;
}

// ---------------------------------------------------------------------------
// Kernel A: per-ray valid count, warp per ray, vectorized per dtype mode.
// ---------------------------------------------------------------------------
__global__ void count_kernel(const void* __restrict__ mask) {
    unsigned mode = mask_mode(mask);
    int ray  = blockIdx.x * 8 + (threadIdx.x >> 5);
    int lane = threadIdx.x & 31;
    int s = 0;
    if (mode == 0u) {
        const uint2* mp = reinterpret_cast<const uint2*>(
            reinterpret_cast<const unsigned char*>(mask) + (size_t)ray * NINTRS);
        uint2 v = mp[lane];
        s = (__popc(__vcmpne4(v.x, 0u)) + __popc(__vcmpne4(v.y, 0u))) >> 3;
    } else if (mode == 1u) {
        const int4* mp = reinterpret_cast<const int4*>(
            reinterpret_cast<const int*>(mask) + (size_t)ray * NINTRS);
        int4 a = mp[lane], b = mp[lane + 32];
        s = (a.x != 0) + (a.y != 0) + (a.z != 0) + (a.w != 0)
          + (b.x != 0) + (b.y != 0) + (b.z != 0) + (b.w != 0);
    } else {
        const float4* mp = reinterpret_cast<const float4*>(
            reinterpret_cast<const float*>(mask) + (size_t)ray * NINTRS);
        float4 a = mp[lane], b = mp[lane + 32];
        s = (a.x != 0.f) + (a.y != 0.f) + (a.z != 0.f) + (a.w != 0.f)
          + (b.x != 0.f) + (b.y != 0.f) + (b.z != 0.f) + (b.w != 0.f);
    }
    #pragma unroll
    for (int o = 16; o; o >>= 1) s += __shfl_down_sync(0xffffffffu, s, o);
    if (lane == 0) g_cnt[ray] = s;
}

// ---------------------------------------------------------------------------
// Kernel B: exclusive scan of per-ray counts (shfl-based, 2 barriers).
// ---------------------------------------------------------------------------
__global__ void scan_kernel() {
    __shared__ int warp_tot[32];
    int t = threadIdx.x, lane = t & 31, w = t >> 5;
    int a[4];
    int s = 0;
    #pragma unroll
    for (int j = 0; j < 4; j++) { a[j] = g_cnt[t * 4 + j]; s += a[j]; }
    int x = s;
    #pragma unroll
    for (int o = 1; o < 32; o <<= 1) {
        int v = __shfl_up_sync(0xffffffffu, x, o);
        if (lane >= o) x += v;
    }
    if (lane == 31) warp_tot[w] = x;
    __syncthreads();
    if (w == 0) {
        int y = warp_tot[lane];
        #pragma unroll
        for (int o = 1; o < 32; o <<= 1) {
            int v = __shfl_up_sync(0xffffffffu, y, o);
            if (lane >= o) y += v;
        }
        warp_tot[lane] = y;
    }
    __syncthreads();
    int base = ((w > 0) ? warp_tot[w - 1] : 0) + (x - s);  // exclusive prefix
    #pragma unroll
    for (int j = 0; j < 4; j++) { g_rowoff[t * 4 + j] = base; base += a[j]; }
}

// ---------------------------------------------------------------------------
// Kernel C: per-ray reduced matrices. CTA handles RPC rays; atoms staged once.
// ---------------------------------------------------------------------------
__global__ void __launch_bounds__(256)
bred_kernel(const float* __restrict__ rays_d, const float* __restrict__ atoms) {
    __shared__ float sa[NATOMS * KSTRIDE];
    __shared__ float ssh[RPC][12];
    int tid = threadIdx.x;

    #pragma unroll
    for (int it = 0; it < DATA_DIM; it++) {
        int idx = tid + it * 256;
        int r = idx / DATA_DIM;
        int c = idx - r * DATA_DIM;
        sa[r * KSTRIDE + c] = atoms[idx];
    }
    if (tid < RPC) {
        int ray = blockIdx.x * RPC + tid;
        float dx = rays_d[ray * 3 + 0], dy = rays_d[ray * 3 + 1], dz = rays_d[ray * 3 + 2];
        float n = sqrtf(dx * dx + dy * dy + dz * dz);
        float inv = 1.0f / n;
        float x = dx * inv, y = dy * inv, z = dz * inv;
        const float C1 = 0.4886025119029199f;
        ssh[tid][0] = 0.28209479177387814f;
        ssh[tid][1] = -C1 * y;
        ssh[tid][2] =  C1 * z;
        ssh[tid][3] = -C1 * x;
        ssh[tid][4] =  1.0925484305920792f * x * y;
        ssh[tid][5] = -1.0925484305920792f * y * z;
        ssh[tid][6] =  0.31539156525252005f * (2.0f * z * z - x * x - y * y);
        ssh[tid][7] = -1.0925484305920792f * x * z;
        ssh[tid][8] =  0.5462742152960396f * (x * x - y * y);
    }
    __syncthreads();

    float ar[DATA_DIM];
    #pragma unroll
    for (int c = 0; c < DATA_DIM; c++) ar[c] = sa[tid * KSTRIDE + c];

    #pragma unroll
    for (int rr = 0; rr < RPC; rr++) {
        int ray = blockIdx.x * RPC + rr;
        float c0 = 0.f, c1 = 0.f, c2 = 0.f;
        #pragma unroll
        for (int s = 0; s < 9; s++) {
            float bs = ssh[rr][s];
            c0 = fmaf(bs, ar[s],      c0);
            c1 = fmaf(bs, ar[9 + s],  c1);
            c2 = fmaf(bs, ar[18 + s], c2);
        }
        g_bred[(size_t)ray * NATOMS + tid] = make_float4(c0, c1, c2, ar[27]);
    }
}

// ---------------------------------------------------------------------------
// Render helpers (inline functions instead of macros; identical semantics).
// ---------------------------------------------------------------------------
__device__ __forceinline__ float4 ldcs4(const float4* p) { return __ldcs(p); }

__device__ __forceinline__ void acc8(float4& acc, const float4& qa, const float4& qb,
                                     const float4* Bt) {
    acc.x = fmaf(qa.x, Bt[0].x, acc.x); acc.y = fmaf(qa.x, Bt[0].y, acc.y);
    acc.z = fmaf(qa.x, Bt[0].z, acc.z); acc.w = fmaf(qa.x, Bt[0].w, acc.w);
    acc.x = fmaf(qa.y, Bt[1].x, acc.x); acc.y = fmaf(qa.y, Bt[1].y, acc.y);
    acc.z = fmaf(qa.y, Bt[1].z, acc.z); acc.w = fmaf(qa.y, Bt[1].w, acc.w);
    acc.x = fmaf(qa.z, Bt[2].x, acc.x); acc.y = fmaf(qa.z, Bt[2].y, acc.y);
    acc.z = fmaf(qa.z, Bt[2].z, acc.z); acc.w = fmaf(qa.z, Bt[2].w, acc.w);
    acc.x = fmaf(qa.w, Bt[3].x, acc.x); acc.y = fmaf(qa.w, Bt[3].y, acc.y);
    acc.z = fmaf(qa.w, Bt[3].z, acc.z); acc.w = fmaf(qa.w, Bt[3].w, acc.w);
    acc.x = fmaf(qb.x, Bt[4].x, acc.x); acc.y = fmaf(qb.x, Bt[4].y, acc.y);
    acc.z = fmaf(qb.x, Bt[4].z, acc.z); acc.w = fmaf(qb.x, Bt[4].w, acc.w);
    acc.x = fmaf(qb.y, Bt[5].x, acc.x); acc.y = fmaf(qb.y, Bt[5].y, acc.y);
    acc.z = fmaf(qb.y, Bt[5].z, acc.z); acc.w = fmaf(qb.y, Bt[5].w, acc.w);
    acc.x = fmaf(qb.z, Bt[6].x, acc.x); acc.y = fmaf(qb.z, Bt[6].y, acc.y);
    acc.z = fmaf(qb.z, Bt[6].z, acc.z); acc.w = fmaf(qb.z, Bt[6].w, acc.w);
    acc.x = fmaf(qb.w, Bt[7].x, acc.x); acc.y = fmaf(qb.w, Bt[7].y, acc.y);
    acc.z = fmaf(qb.w, Bt[7].z, acc.z); acc.w = fmaf(qb.w, Bt[7].w, acc.w);
}

// Butterfly 4-component reduction: 6 SHFL + 6 ADD; component g lands in
// lanes with (lane&7)==0 of octet g; one STS.32 per octet leader.
__device__ __forceinline__ void reduce_store(const float4& acc, int lane,
                                             float* s_resf, int row) {
    float a  = (lane < 16) ? acc.z : acc.x;
    float bb = (lane < 16) ? acc.w : acc.y;
    float ra = __shfl_xor_sync(0xffffffffu, a, 16);
    float rb = __shfl_xor_sync(0xffffffffu, bb, 16);
    float u = ((lane < 16) ? acc.x : acc.z) + ra;
    float v = ((lane < 16) ? acc.y : acc.w) + rb;
    float c  = ((lane & 8) == 0) ? v : u;
    float rc = __shfl_xor_sync(0xffffffffu, c, 8);
    float s = (((lane & 8) == 0) ? u : v) + rc;
    s += __shfl_xor_sync(0xffffffffu, s, 4);
    s += __shfl_xor_sync(0xffffffffu, s, 2);
    s += __shfl_xor_sync(0xffffffffu, s, 1);
    if ((lane & 7) == 0) s_resf[row * 4 + (lane >> 3)] = s;
}

// ---------------------------------------------------------------------------
// Kernel D: fused render. One CTA per ray, 256 threads.
// Direct LDG->register stream, prefetch distance 2, butterfly 4-way reduce.
// ---------------------------------------------------------------------------
__global__ void __launch_bounds__(256)
render_kernel(const float* __restrict__ rays_d,
              const float* __restrict__ queries,
              const void*  __restrict__ mask,
              const float* __restrict__ inter,
              float* __restrict__ out_rgb,
              float* __restrict__ out_alpha,
              float* __restrict__ out_depth)
{
    __shared__ float s_resf[NINTRS * 4];
    __shared__ int   s_wcnt[8];
    __shared__ float s_wprod[8];
    __shared__ float s_red[5][8];

    const int b    = blockIdx.x;
    const int tid  = threadIdx.x;
    const int lane = tid & 31;
    const int wid  = tid >> 5;

    // ---- mask + compaction rank ----
    const unsigned mmode = mask_mode(mask);
    const int mbit = mask_at(mask, mmode, (long)b * NINTRS + tid);
    unsigned bal = __ballot_sync(0xffffffffu, (unsigned)mbit);
    int lprefix = __popc(bal & ((1u << lane) - 1u));
    if (lane == 0) s_wcnt[wid] = __popc(bal);
    __syncthreads();

    int woff = 0, cnt_b = 0;
    #pragma unroll
    for (int w = 0; w < 8; w++) {
        int c = s_wcnt[w];
        if (w < wid) woff += c;
        cnt_b += c;
    }
    const int local_pos = woff + lprefix;
    const int rowbase   = g_rowoff[b];

    // ---- Bred slice (precomputed) ----
    const float4* bred = g_bred + (size_t)b * NATOMS;
    float4 Bt[8];
    #pragma unroll
    for (int j = 0; j < 4; j++) Bt[j]     = bred[lane * 4 + j];
    #pragma unroll
    for (int j = 0; j < 4; j++) Bt[4 + j] = bred[128 + lane * 4 + j];

    // ---- GEMM: warp handles rows wid, wid+8, ...; distance-2 prefetch ----
    const int nrows   = (cnt_b > wid) ? ((cnt_b - wid - 1) >> 3) + 1 : 0;
    const int row_max = (cnt_b > 0) ? cnt_b - 1 : 0;
    const float4* qbase = reinterpret_cast<const float4*>(queries);

    auto qrow = [&](int r) -> const float4* {
        int row = min(wid + 8 * r, row_max);
        return qbase + (size_t)(rowbase + row) * (NATOMS / 4) + lane;
    };

    if (nrows > 0) {
        const float4* p0 = qrow(0);
        const float4* p1 = qrow(1);
        float4 qa0 = ldcs4(p0), qb0 = ldcs4(p0 + 32);
        float4 qa1 = ldcs4(p1), qb1 = ldcs4(p1 + 32);

        for (int r = 0; r < nrows; r += 2) {
            {
                float4 acc = make_float4(0.f, 0.f, 0.f, 0.f);
                acc8(acc, qa0, qb0, Bt);
                const float4* pn = qrow(r + 2);
                qa0 = ldcs4(pn); qb0 = ldcs4(pn + 32);
                reduce_store(acc, lane, s_resf, wid + 8 * r);
            }
            if (r + 1 < nrows) {
                float4 acc = make_float4(0.f, 0.f, 0.f, 0.f);
                acc8(acc, qa1, qb1, Bt);
                const float4* pn = qrow(r + 3);
                qa1 = ldcs4(pn); qb1 = ldcs4(pn + 32);
                reduce_store(acc, lane, s_resf, wid + 8 * (r + 1));
            }
        }
    }
    __syncthreads();

    // ---- rendering: thread i = intersection i ----
    float4 r4 = make_float4(0.f, 0.f, 0.f, 0.f);
    if (mbit) {
        r4.x = s_resf[local_pos * 4 + 0];
        r4.y = s_resf[local_pos * 4 + 1];
        r4.z = s_resf[local_pos * 4 + 2];
        r4.w = s_resf[local_pos * 4 + 3];
    }
    float sigma = fmaxf(r4.w, 0.0f);
    float dx = rays_d[b * 3 + 0], dy = rays_d[b * 3 + 1], dz = rays_d[b * 3 + 2];
    float dn = sqrtf(dx * dx + dy * dy + dz * dz);
    const float* ib = inter + (size_t)b * (NINTRS + 1);
    float t0 = ib[tid], t1 = ib[tid + 1];
    float delta = t1 - t0;
    float alpha = 1.0f - expf(-sigma * delta * dn);
    float p = 1.0f - alpha + 1e-10f;

    // exclusive product scan -> transmittance
    float incl = p;
    #pragma unroll
    for (int o = 1; o < 32; o <<= 1) {
        float v = __shfl_up_sync(0xffffffffu, incl, o);
        if (lane >= o) incl *= v;
    }
    if (lane == 31) s_wprod[wid] = incl;
    float prev = __shfl_up_sync(0xffffffffu, incl, 1);
    float excl_w = (lane == 0) ? 1.0f : prev;
    __syncthreads();
    float wpre = 1.0f;
    #pragma unroll
    for (int w = 0; w < 8; w++) if (w < wid) wpre *= s_wprod[w];
    float trans = wpre * excl_w;
    float wgt = alpha * trans;

    float sgx = 1.0f / (1.0f + expf(-r4.x));
    float sgy = 1.0f / (1.0f + expf(-r4.y));
    float sgz = 1.0f / (1.0f + expf(-r4.z));
    float tmid = 0.5f * (t0 + t1);

    float v0 = wgt, v1 = wgt * sgx, v2 = wgt * sgy, v3 = wgt * sgz, v4 = wgt * tmid;
    #pragma unroll
    for (int o = 16; o; o >>= 1) {
        v0 += __shfl_down_sync(0xffffffffu, v0, o);
        v1 += __shfl_down_sync(0xffffffffu, v1, o);
        v2 += __shfl_down_sync(0xffffffffu, v2, o);
        v3 += __shfl_down_sync(0xffffffffu, v3, o);
        v4 += __shfl_down_sync(0xffffffffu, v4, o);
    }
    if (lane == 0) {
        s_red[0][wid] = v0; s_red[1][wid] = v1; s_red[2][wid] = v2;
        s_red[3][wid] = v3; s_red[4][wid] = v4;
    }
    __syncthreads();
    if (tid == 0) {
        float S = 0.f, R0 = 0.f, R1 = 0.f, R2 = 0.f, D = 0.f;
        #pragma unroll
        for (int w = 0; w < 8; w++) {
            S  += s_red[0][w]; R0 += s_red[1][w]; R1 += s_red[2][w];
            R2 += s_red[3][w]; D  += s_red[4][w];
        }
        float bg = 1.0f - S;
        out_rgb[b * 3 + 0] = R0 + bg;
        out_rgb[b * 3 + 1] = R1 + bg;
        out_rgb[b * 3 + 2] = R2 + bg;
        out_depth[b] = D;
    }
    out_alpha[(size_t)b * NINTRS + tid] = alpha;
}

// ---------------------------------------------------------------------------
// Launch. Inputs bound BY ELEMENT COUNT (ordering-proof):
//   rays_d 12288 | queries 134217728 | mask 1048576 | inter 1052672 | atoms 7168
// ---------------------------------------------------------------------------
extern "C" void kernel_launch(void* const* d_in, const int* in_sizes, int n_in,
                              void* d_out, int out_size) {
    const float* rays_d  = nullptr;
    const float* queries = nullptr;
    const void*  qmask   = nullptr;
    const float* inter   = nullptr;
    const float* atoms   = nullptr;

    for (int i = 0; i < n_in; i++) {
        switch (in_sizes[i]) {
            case 12288:      rays_d  = (const float*)d_in[i]; break;
            case 134217728:  queries = (const float*)d_in[i]; break;
            case 1048576:    qmask   = d_in[i];               break;
            case 1052672:    inter   = (const float*)d_in[i]; break;
            case 7168:       atoms   = (const float*)d_in[i]; break;
            default: break;
        }
    }

    float* out       = (float*)d_out;
    float* out_rgb   = out;
    float* out_alpha = out + BATCH * 3;
    float* out_depth = out + BATCH * 3 + (size_t)BATCH * NINTRS;

    count_kernel<<<BATCH / 8, 256>>>(qmask);
    scan_kernel<<<1, 1024>>>();
    bred_kernel<<<BATCH / RPC, 256>>>(rays_d, atoms);
    render_kernel<<<BATCH, 256>>>(rays_d, queries, qmask, inter,
                                  out_rgb, out_alpha, out_depth);
}